// round 13
// baseline (speedup 1.0000x reference)
#include <cuda_runtime.h>
#include <cstdint>

#define VN 128
#define NTHREADS 256

// collapsed constants: [0:5]gn1 [5:10]gn2 [10:18]d1 [18:26]d2 [26:36]ac
//                      [36]k1 [37]k2 [38]K
__device__ float g_cst[43];
__device__ float g_sums[512 * 28];
__device__ int   g_count = 0;

// ---------------------------------------------------------------------------
// Coalesced task-parallel matvec: out[k] = sum_m W[k*M+m] v[m].
// W may be smem or global (generic pointer).
// ---------------------------------------------------------------------------
__device__ __forceinline__ void mvp(const float* W, const float* v,
                                    float* out, int K, int M, float* psum) {
    const int tid   = threadIdx.x;
    const int nch   = (M < 32) ? M : 32;
    const int chunk = M / nch;
    const int tasks = K * nch;
    const int ps    = nch + 1;
    for (int t = tid; t < tasks; t += NTHREADS) {
        int k = t / nch, c = t - k * nch;
        const float* wr = W + k * M + c;
        float acc = 0.f;
        #pragma unroll 8
        for (int j = 0; j < chunk; j++)
            acc += wr[j * nch] * v[c + j * nch];
        psum[k * ps + c] = acc;
    }
    __syncthreads();
    for (int k = tid; k < K; k += NTHREADS) {
        float acc = 0.f;
        for (int c = 0; c < nch; c++) acc += psum[k * ps + c];
        out[k] = acc;
    }
    __syncthreads();
}

__device__ __forceinline__ float warp_dot(const float* a, const float* b,
                                          int n, int lane) {
    float acc = 0.f;
    for (int i = lane; i < n; i += 32) acc += a[i] * b[i];
    #pragma unroll
    for (int o = 16; o; o >>= 1) acc += __shfl_xor_sync(0xffffffffu, acc, o);
    return acc;
}

__device__ __forceinline__ float prefetch_arr(const float* __restrict__ p,
                                              int n, int tid) {
    float acc = 0.f;
    for (int i = tid; i < n; i += NTHREADS) acc += __ldg(p + i);
    return acc;
}

__device__ __forceinline__ void smem_copy(float* dst,
                                          const float* __restrict__ src,
                                          int n, int tid) {
    for (int i = tid; i < n; i += NTHREADS) dst[i] = src[i];
}

// ---------------------------------------------------------------------------
// Weight collapse (block 0 only). Small weights + biases staged in smem;
// big matrices (f0,f1,g3a,g3b) prefetched to L2. Removes cold-DRAM latency
// from the 17-phase serial chain.
// ---------------------------------------------------------------------------
__device__ void collapse_weights(
    float* sm,
    const float* __restrict__ w_ne0, const float* __restrict__ b_ne0,
    const float* __restrict__ w_ne1, const float* __restrict__ b_ne1,
    const float* __restrict__ w_g1,  const float* __restrict__ b_g1,
    const float* __restrict__ w_g2,  const float* __restrict__ b_g2,
    const float* __restrict__ w_g3a, const float* __restrict__ b_g3a,
    const float* __restrict__ w_g3b, const float* __restrict__ b_g3b,
    const float* __restrict__ w_ce0, const float* __restrict__ b_ce0,
    const float* __restrict__ w_ce1, const float* __restrict__ b_ce1,
    const float* __restrict__ w_f0,  const float* __restrict__ b_f0,
    const float* __restrict__ w_f1,  const float* __restrict__ b_f1,
    const float* __restrict__ w_f2,  const float* __restrict__ b_f2,
    const float* __restrict__ w_f3,  const float* __restrict__ b_f3)
{
    float* v3   = sm;          // 32
    float* v2   = v3 + 32;     // 64
    float* v1   = v2 + 64;     // 128
    float* wfv  = v1 + 128;    // 160 (144 used)
    float* t16  = wfv + 160;   // 32
    float* evec = t16 + 32;    // 256
    float* fvec = evec + 256;  // 128
    float* tmp64= fvec + 128;  // 64
    float* a1   = tmp64 + 64;  // 32
    float* a2   = a1 + 32;     // 32
    float* g1a  = a2 + 32;     // 40
    float* g1b  = g1a + 40;    // 40
    float* ng1  = g1b + 40;    // 64
    float* ng2  = ng1 + 64;    // 64
    float* d1v  = ng2 + 64;    // 8
    float* d2v  = d1v + 8;     // 8
    float* acv  = d2v + 8;     // 12
    float* kres = acv + 12;    // 16
    float* psum = kres + 16;   // 8448
    float* sw_f2  = psum + 8448;     // 2048
    float* sw_g2  = sw_f2 + 2048;    // 2048
    float* sw_g1  = sw_g2 + 2048;    // 1184
    float* sw_ne1 = sw_g1 + 1184;    // 2048
    float* sw_ne0 = sw_ne1 + 2048;   // 512
    float* sw_ce0 = sw_ne0 + 512;    // 320
    float* sw_ce1 = sw_ce0 + 320;    // 512
    float* sb     = sw_ce1 + 512;    // 849 biases (see offsets below)
    // total 19149 floats < 22272 budget

    const int tid = threadIdx.x, wid = tid >> 5, lane = tid & 31;

    // --- stage small weights + biases in smem; prefetch big ones into L2 ---
    {
        float acc = 0.f;
        acc += prefetch_arr(w_f0, 144 * 128, tid);
        acc += prefetch_arr(w_f1, 128 * 64, tid);
        acc += prefetch_arr(w_g3a, 128 * 256, tid);
        acc += prefetch_arr(w_g3b, 256 * 128, tid);

        smem_copy(sw_f2, w_f2, 64 * 32, tid);
        smem_copy(sw_g2, w_g2, 32 * 64, tid);
        smem_copy(sw_g1, w_g1, 37 * 32, tid);
        smem_copy(sw_ne1, w_ne1, 64 * 32, tid);
        smem_copy(sw_ne0, w_ne0, 8 * 64, tid);
        smem_copy(sw_ce0, w_ce0, 10 * 32, tid);
        smem_copy(sw_ce1, w_ce1, 32 * 16, tid);
        // biases: f2[0:32) f1[32:96) f0[96:224) ce0[224:256) ce1[256:272)
        //         g2[272:336) g3a[336:592) g3b[592:720) g1[720:752)
        //         ne0[752:816) ne1[816:848) f3[848]
        smem_copy(sb + 0,   b_f2, 32, tid);
        smem_copy(sb + 32,  b_f1, 64, tid);
        smem_copy(sb + 96,  b_f0, 128, tid);
        smem_copy(sb + 224, b_ce0, 32, tid);
        smem_copy(sb + 256, b_ce1, 16, tid);
        smem_copy(sb + 272, b_g2, 64, tid);
        smem_copy(sb + 336, b_g3a, 256, tid);
        smem_copy(sb + 592, b_g3b, 128, tid);
        smem_copy(sb + 720, b_g1, 32, tid);
        smem_copy(sb + 752, b_ne0, 64, tid);
        smem_copy(sb + 816, b_ne1, 32, tid);
        if (tid == 0) sb[848] = b_f3[0];
        if (tid < 32) v3[tid] = w_f3[tid];
        psum[tid] = acc;   // keep prefetch loads alive
    }
    __syncthreads();

    mvp(sw_f2, v3, v2, 64, 32, psum);
    mvp(w_f1, v2, v1, 128, 64, psum);         // L2-hot
    mvp(w_f0, v1, wfv, 144, 128, psum);       // L2-hot; [0:128]=Wfg [128:144]=Wfc
    mvp(w_g3b, wfv, evec, 256, 128, psum);    // L2-hot
    mvp(sw_ce1, wfv + 128, t16, 32, 16, psum);
    mvp(w_g3a, evec, fvec, 128, 256, psum);   // L2-hot
    mvp(sw_ce0, t16, acv, 10, 32, psum);
    if (tid < 64) tmp64[tid] = fvec[tid] + fvec[64 + tid];
    __syncthreads();
    mvp(sw_g2, tmp64, a1, 32, 64, psum);
    mvp(sw_g2, fvec + 64, a2, 32, 64, psum);
    if (tid < 32) a2[tid] = -a2[tid];
    __syncthreads();
    mvp(sw_g1, a1, g1a, 37, 32, psum);
    mvp(sw_g1, a2, g1b, 37, 32, psum);
    mvp(sw_ne1, g1a + 5, ng1, 64, 32, psum);
    mvp(sw_ne1, g1b + 5, ng2, 64, 32, psum);
    mvp(sw_ne0, ng1, d1v, 8, 64, psum);
    mvp(sw_ne0, ng2, d2v, 8, 64, psum);

    // all 14 bias dots (smem sources) in one parallel phase
    for (int o = wid; o < 14; o += 8) {
        float r;
        switch (o) {
            case 0:  r = warp_dot(sb + 0, v3, 32, lane); break;
            case 1:  r = warp_dot(sb + 32, v2, 64, lane); break;
            case 2:  r = warp_dot(sb + 96, v1, 128, lane); break;
            case 3:  r = warp_dot(sb + 224, t16, 32, lane); break;
            case 4:  r = warp_dot(sb + 256, wfv + 128, 16, lane); break;
            case 5:  r = warp_dot(sb + 272, fvec, 64, lane); break;
            case 6:  r = warp_dot(sb + 336, evec, 256, lane); break;
            case 7:  r = warp_dot(sb + 592, wfv, 128, lane); break;
            case 8:  r = warp_dot(sb + 720, a1, 32, lane); break;
            case 9:  r = warp_dot(sb + 752, ng1, 64, lane); break;
            case 10: r = warp_dot(sb + 816, g1a + 5, 32, lane); break;
            case 11: r = warp_dot(sb + 720, a2, 32, lane); break;
            case 12: r = warp_dot(sb + 752, ng2, 64, lane); break;
            default: r = warp_dot(sb + 816, g1b + 5, 32, lane); break;
        }
        if (lane == 0) kres[o] = r;
    }
    __syncthreads();

    if (tid < 5)  { g_cst[tid] = g1a[tid]; g_cst[5 + tid] = g1b[tid]; }
    if (tid < 8)  { g_cst[10 + tid] = d1v[tid]; g_cst[18 + tid] = d2v[tid]; }
    if (tid < 10) g_cst[26 + tid] = acv[tid];
    if (tid == 0) {
        g_cst[36] = kres[8] + kres[9] + kres[10];
        g_cst[37] = kres[11] + kres[12] + kres[13];
        g_cst[38] = kres[0] + kres[1] + kres[2] + kres[3] + kres[4]
                  + kres[5] + kres[6] + kres[7] + sb[848];
    }
}

// ---------------------------------------------------------------------------
// grid 513. Block 0: smem-staged collapse. Blocks 1..512: R1-proven streaming
// + chain + 28 weight-independent sums -> g_sums. Last block combines -> out.
// smem floats: 22272 = 89088 B (2 blocks/SM)
// ---------------------------------------------------------------------------
#define SMEM_FLOATS (16384 + 5120 + 512 + 256)
#define SMEM_BYTES  (SMEM_FLOATS * 4)

__global__ __launch_bounds__(NTHREADS, 2) void gnn_fused(
    const float* __restrict__ edges,
    const float* __restrict__ nodes,
    const float* __restrict__ nparams,
    const float* __restrict__ cond,
    float* __restrict__ out,
    const float* w_ne0, const float* b_ne0, const float* w_ne1, const float* b_ne1,
    const float* w_g1,  const float* b_g1,  const float* w_g2,  const float* b_g2,
    const float* w_g3a, const float* b_g3a, const float* w_g3b, const float* b_g3b,
    const float* w_ce0, const float* b_ce0, const float* w_ce1, const float* b_ce1,
    const float* w_f0,  const float* b_f0,  const float* w_f1,  const float* b_f1,
    const float* w_f2,  const float* b_f2,  const float* w_f3,  const float* b_f3)
{
    extern __shared__ float sm[];
    const int tid = threadIdx.x;
    const int wid = tid >> 5, lane = tid & 31;

    if (blockIdx.x == 0) {
        collapse_weights(sm,
                         w_ne0, b_ne0, w_ne1, b_ne1, w_g1, b_g1, w_g2, b_g2,
                         w_g3a, b_g3a, w_g3b, b_g3b, w_ce0, b_ce0, w_ce1, b_ce1,
                         w_f0, b_f0, w_f1, b_f1, w_f2, b_f2, w_f3, b_f3);
    } else {
        const int b = blockIdx.x - 1;
        float* Asum  = sm;               // 16384
        float* stage = Asum + 16384;     // 5120 (8 rows x 640)
        float* deg   = stage + 5120;     // 128
        float* w0    = deg + 128;        // 128
        float* rA    = w0 + 128;         // 128
        float* rB    = rA + 128;         // 128

        // ---- Phase 1 (R1-proven): Asum[i][j] = sum_{t=1..4} edges[b,i,j,t]
        const float4* src = (const float4*)(edges + (size_t)b * VN * VN * 5);
        float4* st4 = (float4*)stage;
        for (int ch = 0; ch < 16; ch++) {
            const float4* s4 = src + ch * 1280;   // 8 rows * 160 f4
            #pragma unroll
            for (int k = 0; k < 5; k++)
                st4[tid + NTHREADS * k] = s4[tid + NTHREADS * k];
            __syncthreads();
            #pragma unroll
            for (int k = 0; k < 4; k++) {
                int idx = tid + NTHREADS * k;     // 0..1023
                int ri  = idx >> 7;
                int j   = idx & 127;
                const float* s = stage + ri * 640 + 5 * j;
                Asum[(ch * 8 + ri) * VN + j] = s[1] + s[2] + s[3] + s[4];
            }
            __syncthreads();
        }

        // ---- deg[i] = row sum; w0 = 1/(V*deg) ----
        for (int i = wid; i < VN; i += 8) {
            float acc = 0.f;
            #pragma unroll
            for (int u = 0; u < 4; u++) acc += Asum[i * VN + lane + 32 * u];
            #pragma unroll
            for (int o = 16; o; o >>= 1)
                acc += __shfl_xor_sync(0xffffffffu, acc, o);
            if (lane == 0) {
                float d = fmaxf(acc, 1e-8f);
                deg[i] = d;
                w0[i]  = 1.f / (d * (float)VN);
            }
        }
        __syncthreads();

        // ---- r1 = Asum^T w0 ; r2 ; r3 ----
        if (tid < VN) {
            float acc = 0.f;
            #pragma unroll 8
            for (int i = 0; i < VN; i++) acc += Asum[i * VN + tid] * w0[i];
            rA[tid] = acc;                       // r1
        }
        __syncthreads();
        if (tid < VN) w0[tid] = rA[tid] / deg[tid];
        __syncthreads();
        if (tid < VN) {
            float acc = 0.f;
            #pragma unroll 8
            for (int i = 0; i < VN; i++) acc += Asum[i * VN + tid] * w0[i];
            rA[tid] = acc;                       // r2
        }
        __syncthreads();
        if (tid < VN) w0[tid] = rA[tid] / deg[tid];
        __syncthreads();
        if (tid < VN) {
            float acc = 0.f;
            #pragma unroll 8
            for (int i = 0; i < VN; i++) acc += Asum[i * VN + tid] * w0[i];
            rB[tid] = acc;                       // r3
        }
        __syncthreads();

        // ---- 28 weight-independent sums -> g_sums ----
        for (int o = wid; o < 28; o += 8) {
            const float* r = (o >= 14) ? rB : rA;
            int m = (o >= 14) ? o - 14 : o;
            float acc = 0.f;
            #pragma unroll 4
            for (int j = lane; j < VN; j += 32) {
                float x;
                if (m < 5)       x = nodes[((size_t)b * VN + j) * 5 + m];
                else if (m < 13) x = nparams[((size_t)b * VN + j) * 8 + (m - 5)];
                else             x = 1.f;
                acc += r[j] * x;
            }
            #pragma unroll
            for (int off = 16; off; off >>= 1)
                acc += __shfl_xor_sync(0xffffffffu, acc, off);
            if (lane == 0) g_sums[b * 28 + o] = acc;
        }
    }

    // ---- last-block combine ----
    __threadfence();
    __syncthreads();
    __shared__ int s_old;
    if (tid == 0) s_old = atomicAdd(&g_count, 1);
    __syncthreads();
    if (s_old == 512) {
        float c[43];
        #pragma unroll
        for (int i = 0; i < 43; i++) c[i] = __ldcg(&g_cst[i]);
        for (int b2 = tid; b2 < 512; b2 += NTHREADS) {
            const float* S = &g_sums[b2 * 28];
            float acc = c[38] + c[36] * __ldcg(&S[13]) + c[37] * __ldcg(&S[27]);
            #pragma unroll
            for (int m = 0; m < 5; m++)
                acc += c[m] * __ldcg(&S[m]) + c[5 + m] * __ldcg(&S[14 + m]);
            #pragma unroll
            for (int m = 0; m < 8; m++)
                acc += c[10 + m] * __ldcg(&S[5 + m]) + c[18 + m] * __ldcg(&S[19 + m]);
            const float* cd = cond + (size_t)b2 * 10;
            #pragma unroll
            for (int m = 0; m < 10; m++) acc += c[26 + m] * cd[m];
            out[b2] = acc;
        }
        if (tid == 0) g_count = 0;   // reset for next graph replay
    }
}

extern "C" void kernel_launch(void* const* d_in, const int* in_sizes, int n_in,
                              void* d_out, int out_size) {
    cudaFuncSetAttribute(gnn_fused, cudaFuncAttributeMaxDynamicSharedMemorySize,
                         SMEM_BYTES);

    gnn_fused<<<513, NTHREADS, SMEM_BYTES>>>(
        (const float*)d_in[0], (const float*)d_in[1],
        (const float*)d_in[2], (const float*)d_in[3],
        (float*)d_out,
        (const float*)d_in[4],  (const float*)d_in[5],
        (const float*)d_in[6],  (const float*)d_in[7],
        (const float*)d_in[8],  (const float*)d_in[9],
        (const float*)d_in[10], (const float*)d_in[11],
        (const float*)d_in[12], (const float*)d_in[13],
        (const float*)d_in[14], (const float*)d_in[15],
        (const float*)d_in[16], (const float*)d_in[17],
        (const float*)d_in[18], (const float*)d_in[19],
        (const float*)d_in[20], (const float*)d_in[21],
        (const float*)d_in[22], (const float*)d_in[23],
        (const float*)d_in[24], (const float*)d_in[25],
        (const float*)d_in[26], (const float*)d_in[27]);
}

// round 14
// speedup vs baseline: 1.5548x; 1.5548x over previous
#include <cuda_runtime.h>
#include <cstdint>

#define VN 128
#define NTHREADS 256

// collapsed constants: [0:5]gn1 [5:10]gn2 [10:18]d1 [18:26]d2 [26:36]ac
//                      [36]k1 [37]k2 [38]K
__device__ float g_cst[43];
__device__ float g_sums[512 * 28];
__device__ int   g_count = 0;

__device__ __forceinline__ void l2_prefetch(const void* p) {
    asm volatile("prefetch.global.L2 [%0];" :: "l"(p));
}

// ---------------------------------------------------------------------------
// Coalesced task-parallel matvec: out[k] = sum_m W[k*M+m] v[m].
// ---------------------------------------------------------------------------
__device__ __forceinline__ void mvp(const float* W, const float* v,
                                    float* out, int K, int M, float* psum) {
    const int tid   = threadIdx.x;
    const int nch   = (M < 32) ? M : 32;
    const int chunk = M / nch;
    const int tasks = K * nch;
    const int ps    = nch + 1;
    for (int t = tid; t < tasks; t += NTHREADS) {
        int k = t / nch, c = t - k * nch;
        const float* wr = W + k * M + c;
        float acc = 0.f;
        #pragma unroll 8
        for (int j = 0; j < chunk; j++)
            acc += wr[j * nch] * v[c + j * nch];
        psum[k * ps + c] = acc;
    }
    __syncthreads();
    for (int k = tid; k < K; k += NTHREADS) {
        float acc = 0.f;
        for (int c = 0; c < nch; c++) acc += psum[k * ps + c];
        out[k] = acc;
    }
    __syncthreads();
}

__device__ __forceinline__ float warp_dot(const float* a, const float* b,
                                          int n, int lane) {
    float acc = 0.f;
    for (int i = lane; i < n; i += 32) acc += a[i] * b[i];
    #pragma unroll
    for (int o = 16; o; o >>= 1) acc += __shfl_xor_sync(0xffffffffu, acc, o);
    return acc;
}

__device__ __forceinline__ void smem_copy(float* dst,
                                          const float* __restrict__ src,
                                          int n, int tid) {
    for (int i = tid; i < n; i += NTHREADS) dst[i] = src[i];
}

// ---------------------------------------------------------------------------
// Weight collapse (block 0 only). Small weights + biases staged in smem
// (~35KB, cheap). Big matrices read from L2 (prefetched by blocks 1..12).
// ---------------------------------------------------------------------------
__device__ void collapse_weights(
    float* sm,
    const float* __restrict__ w_ne0, const float* __restrict__ b_ne0,
    const float* __restrict__ w_ne1, const float* __restrict__ b_ne1,
    const float* __restrict__ w_g1,  const float* __restrict__ b_g1,
    const float* __restrict__ w_g2,  const float* __restrict__ b_g2,
    const float* __restrict__ w_g3a, const float* __restrict__ b_g3a,
    const float* __restrict__ w_g3b, const float* __restrict__ b_g3b,
    const float* __restrict__ w_ce0, const float* __restrict__ b_ce0,
    const float* __restrict__ w_ce1, const float* __restrict__ b_ce1,
    const float* __restrict__ w_f0,  const float* __restrict__ b_f0,
    const float* __restrict__ w_f1,  const float* __restrict__ b_f1,
    const float* __restrict__ w_f2,  const float* __restrict__ b_f2,
    const float* __restrict__ w_f3,  const float* __restrict__ b_f3)
{
    float* v3   = sm;          // 32
    float* v2   = v3 + 32;     // 64
    float* v1   = v2 + 64;     // 128
    float* wfv  = v1 + 128;    // 160 (144 used)
    float* t16  = wfv + 160;   // 32
    float* evec = t16 + 32;    // 256
    float* fvec = evec + 256;  // 128
    float* tmp64= fvec + 128;  // 64
    float* a1   = tmp64 + 64;  // 32
    float* a2   = a1 + 32;     // 32
    float* g1a  = a2 + 32;     // 40
    float* g1b  = g1a + 40;    // 40
    float* ng1  = g1b + 40;    // 64
    float* ng2  = ng1 + 64;    // 64
    float* d1v  = ng2 + 64;    // 8
    float* d2v  = d1v + 8;     // 8
    float* acv  = d2v + 8;     // 12
    float* kres = acv + 12;    // 16
    float* psum = kres + 16;   // 8448
    float* sw_f2  = psum + 8448;     // 2048
    float* sw_g2  = sw_f2 + 2048;    // 2048
    float* sw_g1  = sw_g2 + 2048;    // 1184
    float* sw_ne1 = sw_g1 + 1184;    // 2048
    float* sw_ne0 = sw_ne1 + 2048;   // 512
    float* sw_ce0 = sw_ne0 + 512;    // 320
    float* sw_ce1 = sw_ce0 + 320;    // 512
    float* sb     = sw_ce1 + 512;    // 849 biases

    const int tid = threadIdx.x, wid = tid >> 5, lane = tid & 31;

    // --- stage small weights + biases in smem (coalesced, ~35KB) ---
    smem_copy(sw_f2, w_f2, 64 * 32, tid);
    smem_copy(sw_g2, w_g2, 32 * 64, tid);
    smem_copy(sw_g1, w_g1, 37 * 32, tid);
    smem_copy(sw_ne1, w_ne1, 64 * 32, tid);
    smem_copy(sw_ne0, w_ne0, 8 * 64, tid);
    smem_copy(sw_ce0, w_ce0, 10 * 32, tid);
    smem_copy(sw_ce1, w_ce1, 32 * 16, tid);
    smem_copy(sb + 0,   b_f2, 32, tid);
    smem_copy(sb + 32,  b_f1, 64, tid);
    smem_copy(sb + 96,  b_f0, 128, tid);
    smem_copy(sb + 224, b_ce0, 32, tid);
    smem_copy(sb + 256, b_ce1, 16, tid);
    smem_copy(sb + 272, b_g2, 64, tid);
    smem_copy(sb + 336, b_g3a, 256, tid);
    smem_copy(sb + 592, b_g3b, 128, tid);
    smem_copy(sb + 720, b_g1, 32, tid);
    smem_copy(sb + 752, b_ne0, 64, tid);
    smem_copy(sb + 816, b_ne1, 32, tid);
    if (tid == 0) sb[848] = b_f3[0];
    if (tid < 32) v3[tid] = w_f3[tid];
    __syncthreads();

    mvp(sw_f2, v3, v2, 64, 32, psum);
    mvp(w_f1, v2, v1, 128, 64, psum);         // L2-hot (prefetched)
    mvp(w_f0, v1, wfv, 144, 128, psum);       // L2-hot; [0:128]=Wfg [128:144]=Wfc
    mvp(w_g3b, wfv, evec, 256, 128, psum);    // L2-hot
    mvp(sw_ce1, wfv + 128, t16, 32, 16, psum);
    mvp(w_g3a, evec, fvec, 128, 256, psum);   // L2-hot
    mvp(sw_ce0, t16, acv, 10, 32, psum);
    if (tid < 64) tmp64[tid] = fvec[tid] + fvec[64 + tid];
    __syncthreads();
    mvp(sw_g2, tmp64, a1, 32, 64, psum);
    mvp(sw_g2, fvec + 64, a2, 32, 64, psum);
    if (tid < 32) a2[tid] = -a2[tid];
    __syncthreads();
    mvp(sw_g1, a1, g1a, 37, 32, psum);
    mvp(sw_g1, a2, g1b, 37, 32, psum);
    mvp(sw_ne1, g1a + 5, ng1, 64, 32, psum);
    mvp(sw_ne1, g1b + 5, ng2, 64, 32, psum);
    mvp(sw_ne0, ng1, d1v, 8, 64, psum);
    mvp(sw_ne0, ng2, d2v, 8, 64, psum);

    // all 14 bias dots (smem sources) in one parallel phase
    for (int o = wid; o < 14; o += 8) {
        float r;
        switch (o) {
            case 0:  r = warp_dot(sb + 0, v3, 32, lane); break;
            case 1:  r = warp_dot(sb + 32, v2, 64, lane); break;
            case 2:  r = warp_dot(sb + 96, v1, 128, lane); break;
            case 3:  r = warp_dot(sb + 224, t16, 32, lane); break;
            case 4:  r = warp_dot(sb + 256, wfv + 128, 16, lane); break;
            case 5:  r = warp_dot(sb + 272, fvec, 64, lane); break;
            case 6:  r = warp_dot(sb + 336, evec, 256, lane); break;
            case 7:  r = warp_dot(sb + 592, wfv, 128, lane); break;
            case 8:  r = warp_dot(sb + 720, a1, 32, lane); break;
            case 9:  r = warp_dot(sb + 752, ng1, 64, lane); break;
            case 10: r = warp_dot(sb + 816, g1a + 5, 32, lane); break;
            case 11: r = warp_dot(sb + 720, a2, 32, lane); break;
            case 12: r = warp_dot(sb + 752, ng2, 64, lane); break;
            default: r = warp_dot(sb + 816, g1b + 5, 32, lane); break;
        }
        if (lane == 0) kres[o] = r;
    }
    __syncthreads();

    if (tid < 5)  { g_cst[tid] = g1a[tid]; g_cst[5 + tid] = g1b[tid]; }
    if (tid < 8)  { g_cst[10 + tid] = d1v[tid]; g_cst[18 + tid] = d2v[tid]; }
    if (tid < 10) g_cst[26 + tid] = acv[tid];
    if (tid == 0) {
        g_cst[36] = kres[8] + kres[9] + kres[10];
        g_cst[37] = kres[11] + kres[12] + kres[13];
        g_cst[38] = kres[0] + kres[1] + kres[2] + kres[3] + kres[4]
                  + kres[5] + kres[6] + kres[7] + sb[848];
    }
}

// ---------------------------------------------------------------------------
// grid 513. Block 0: collapse (big weights L2-hot via distributed prefetch).
// Blocks 1..12: prefetch big-weight lines into L2 (1 instr/thread), then
// stream like everyone else. Blocks 1..512: R1-proven streaming (__ldcs,
// evict-first) + chain + 28 sums -> g_sums. Last block combines -> out.
// smem floats: 22272 = 89088 B (2 blocks/SM)
// ---------------------------------------------------------------------------
#define SMEM_FLOATS (16384 + 5120 + 512 + 256)
#define SMEM_BYTES  (SMEM_FLOATS * 4)

__global__ __launch_bounds__(NTHREADS, 2) void gnn_fused(
    const float* __restrict__ edges,
    const float* __restrict__ nodes,
    const float* __restrict__ nparams,
    const float* __restrict__ cond,
    float* __restrict__ out,
    const float* w_ne0, const float* b_ne0, const float* w_ne1, const float* b_ne1,
    const float* w_g1,  const float* b_g1,  const float* w_g2,  const float* b_g2,
    const float* w_g3a, const float* b_g3a, const float* w_g3b, const float* b_g3b,
    const float* w_ce0, const float* b_ce0, const float* w_ce1, const float* b_ce1,
    const float* w_f0,  const float* b_f0,  const float* w_f1,  const float* b_f1,
    const float* w_f2,  const float* b_f2,  const float* w_f3,  const float* b_f3)
{
    extern __shared__ float sm[];
    const int tid = threadIdx.x;
    const int wid = tid >> 5, lane = tid & 31;

    if (blockIdx.x == 0) {
        collapse_weights(sm,
                         w_ne0, b_ne0, w_ne1, b_ne1, w_g1, b_g1, w_g2, b_g2,
                         w_g3a, b_g3a, w_g3b, b_g3b, w_ce0, b_ce0, w_ce1, b_ce1,
                         w_f0, b_f0, w_f1, b_f1, w_f2, b_f2, w_f3, b_f3);
    } else {
        // ---- distributed L2 prefetch of big weights (blocks 1..12) ----
        // line ranges (128B lines): f0 [0,576) f1 [576,832) g3a [832,1856)
        //                           g3b [1856,2880)
        if (blockIdx.x <= 12) {
            int L = (int)(blockIdx.x - 1) * NTHREADS + tid;   // 0..3071
            if (L < 2880) {
                const char* p;
                if (L < 576)       p = (const char*)w_f0  + (size_t)L * 128;
                else if (L < 832)  p = (const char*)w_f1  + (size_t)(L - 576) * 128;
                else if (L < 1856) p = (const char*)w_g3a + (size_t)(L - 832) * 128;
                else               p = (const char*)w_g3b + (size_t)(L - 1856) * 128;
                l2_prefetch(p);
            }
        }

        const int b = blockIdx.x - 1;
        float* Asum  = sm;               // 16384
        float* stage = Asum + 16384;     // 5120 (8 rows x 640)
        float* deg   = stage + 5120;     // 128
        float* w0    = deg + 128;        // 128
        float* rA    = w0 + 128;         // 128
        float* rB    = rA + 128;         // 128

        // ---- Phase 1 (R1-proven): Asum[i][j] = sum_{t=1..4} edges[b,i,j,t]
        //      __ldcs: evict-first so edges don't flush weights from L2 ----
        const float4* src = (const float4*)(edges + (size_t)b * VN * VN * 5);
        float4* st4 = (float4*)stage;
        for (int ch = 0; ch < 16; ch++) {
            const float4* s4 = src + ch * 1280;   // 8 rows * 160 f4
            #pragma unroll
            for (int k = 0; k < 5; k++)
                st4[tid + NTHREADS * k] = __ldcs(s4 + tid + NTHREADS * k);
            __syncthreads();
            #pragma unroll
            for (int k = 0; k < 4; k++) {
                int idx = tid + NTHREADS * k;     // 0..1023
                int ri  = idx >> 7;
                int j   = idx & 127;
                const float* s = stage + ri * 640 + 5 * j;
                Asum[(ch * 8 + ri) * VN + j] = s[1] + s[2] + s[3] + s[4];
            }
            __syncthreads();
        }

        // ---- deg[i] = row sum; w0 = 1/(V*deg) ----
        for (int i = wid; i < VN; i += 8) {
            float acc = 0.f;
            #pragma unroll
            for (int u = 0; u < 4; u++) acc += Asum[i * VN + lane + 32 * u];
            #pragma unroll
            for (int o = 16; o; o >>= 1)
                acc += __shfl_xor_sync(0xffffffffu, acc, o);
            if (lane == 0) {
                float d = fmaxf(acc, 1e-8f);
                deg[i] = d;
                w0[i]  = 1.f / (d * (float)VN);
            }
        }
        __syncthreads();

        // ---- r1 = Asum^T w0 ; r2 ; r3 ----
        if (tid < VN) {
            float acc = 0.f;
            #pragma unroll 8
            for (int i = 0; i < VN; i++) acc += Asum[i * VN + tid] * w0[i];
            rA[tid] = acc;                       // r1
        }
        __syncthreads();
        if (tid < VN) w0[tid] = rA[tid] / deg[tid];
        __syncthreads();
        if (tid < VN) {
            float acc = 0.f;
            #pragma unroll 8
            for (int i = 0; i < VN; i++) acc += Asum[i * VN + tid] * w0[i];
            rA[tid] = acc;                       // r2
        }
        __syncthreads();
        if (tid < VN) w0[tid] = rA[tid] / deg[tid];
        __syncthreads();
        if (tid < VN) {
            float acc = 0.f;
            #pragma unroll 8
            for (int i = 0; i < VN; i++) acc += Asum[i * VN + tid] * w0[i];
            rB[tid] = acc;                       // r3
        }
        __syncthreads();

        // ---- 28 weight-independent sums -> g_sums ----
        for (int o = wid; o < 28; o += 8) {
            const float* r = (o >= 14) ? rB : rA;
            int m = (o >= 14) ? o - 14 : o;
            float acc = 0.f;
            #pragma unroll 4
            for (int j = lane; j < VN; j += 32) {
                float x;
                if (m < 5)       x = nodes[((size_t)b * VN + j) * 5 + m];
                else if (m < 13) x = nparams[((size_t)b * VN + j) * 8 + (m - 5)];
                else             x = 1.f;
                acc += r[j] * x;
            }
            #pragma unroll
            for (int off = 16; off; off >>= 1)
                acc += __shfl_xor_sync(0xffffffffu, acc, off);
            if (lane == 0) g_sums[b * 28 + o] = acc;
        }
    }

    // ---- last-block combine ----
    __threadfence();
    __syncthreads();
    __shared__ int s_old;
    if (tid == 0) s_old = atomicAdd(&g_count, 1);
    __syncthreads();
    if (s_old == 512) {
        float c[43];
        #pragma unroll
        for (int i = 0; i < 43; i++) c[i] = __ldcg(&g_cst[i]);
        for (int b2 = tid; b2 < 512; b2 += NTHREADS) {
            const float* S = &g_sums[b2 * 28];
            float acc = c[38] + c[36] * __ldcg(&S[13]) + c[37] * __ldcg(&S[27]);
            #pragma unroll
            for (int m = 0; m < 5; m++)
                acc += c[m] * __ldcg(&S[m]) + c[5 + m] * __ldcg(&S[14 + m]);
            #pragma unroll
            for (int m = 0; m < 8; m++)
                acc += c[10 + m] * __ldcg(&S[5 + m]) + c[18 + m] * __ldcg(&S[19 + m]);
            const float* cd = cond + (size_t)b2 * 10;
            #pragma unroll
            for (int m = 0; m < 10; m++) acc += c[26 + m] * cd[m];
            out[b2] = acc;
        }
        if (tid == 0) g_count = 0;   // reset for next graph replay
    }
}

extern "C" void kernel_launch(void* const* d_in, const int* in_sizes, int n_in,
                              void* d_out, int out_size) {
    cudaFuncSetAttribute(gnn_fused, cudaFuncAttributeMaxDynamicSharedMemorySize,
                         SMEM_BYTES);

    gnn_fused<<<513, NTHREADS, SMEM_BYTES>>>(
        (const float*)d_in[0], (const float*)d_in[1],
        (const float*)d_in[2], (const float*)d_in[3],
        (float*)d_out,
        (const float*)d_in[4],  (const float*)d_in[5],
        (const float*)d_in[6],  (const float*)d_in[7],
        (const float*)d_in[8],  (const float*)d_in[9],
        (const float*)d_in[10], (const float*)d_in[11],
        (const float*)d_in[12], (const float*)d_in[13],
        (const float*)d_in[14], (const float*)d_in[15],
        (const float*)d_in[16], (const float*)d_in[17],
        (const float*)d_in[18], (const float*)d_in[19],
        (const float*)d_in[20], (const float*)d_in[21],
        (const float*)d_in[22], (const float*)d_in[23],
        (const float*)d_in[24], (const float*)d_in[25],
        (const float*)d_in[26], (const float*)d_in[27]);
}